// round 11
// baseline (speedup 1.0000x reference)
#include <cuda_runtime.h>

// Problem constants (fixed-shape problem)
#define NVOC 100     // vocab
#define NL   5       // gate layers
#define NH   32      // gate hidden (== warp size)
#define NSD  16      // s-dim
#define NG   8192    // segments
#define NEMB 128     // embedding dim
#define NHID 64      // EMB/2
#define TPB  512     // threads per CTA
#define NWPC (TPB/32)

// Scratch (__device__ globals; no allocations allowed)
__device__ float    g_scale[NVOC];        // per-vocab final gate product
__device__ float    g_E1[NVOC * NHID];    // emb @ pw1 (100 x 64)
__device__ float    g_W[NG * NVOC];       // per-(segment, vocab) accumulator
__device__ unsigned g_bar0, g_bar1, g_done;   // zero-init; reset each replay

// Grid-wide barrier: bar.sync gives CTA-scope ordering, thread0's fenced
// atomic publishes it GPU-scope (cumulative fences, same as CG grid.sync).
// Safe because resource math guarantees all CTAs co-resident (2 CTAs/SM,
// <=64 regs via launch_bounds, ~33KB static smem).
__device__ __forceinline__ void grid_barrier(unsigned* bar) {
    __syncthreads();
    if (threadIdx.x == 0) {
        __threadfence();
        atomicAdd(bar, 1u);
        while (*(volatile unsigned*)bar < gridDim.x) __nanosleep(64);
        __threadfence();
    }
    __syncthreads();
}

__global__ void __launch_bounds__(TPB, 2)
fused_kernel(const int* __restrict__ atoms, const int* __restrict__ batch,
             const float* __restrict__ emb, const float* __restrict__ w1,
             const float* __restrict__ b1,  const float* __restrict__ w2,
             const float* __restrict__ b2,  const float* __restrict__ pw1,
             const float* __restrict__ pb1, const float* __restrict__ pw2,
             const float* __restrict__ pb2, float* __restrict__ out, int N) {
    __shared__ float E1s[NVOC * NHID];     // 25.6 KB
    __shared__ float wrow[NWPC][NVOC];     // 6.4 KB
    __shared__ float s_scale[NVOC];
    __shared__ float pb1s[NHID], pw2s[NHID];

    const int tid     = threadIdx.x;
    const int warp    = tid >> 5, lane = tid & 31;
    const int gthread = blockIdx.x * TPB + tid;
    const int gsize   = gridDim.x * TPB;

    // ---------------- Phase A: zero W; CTA0 -> scale; CTA1 -> E1 -----------
    const float4 z4 = make_float4(0.f, 0.f, 0.f, 0.f);
    for (int i = gthread; i < NG * NVOC / 4; i += gsize)
        reinterpret_cast<float4*>(g_W)[i] = z4;

    if (blockIdx.x == 0) {
        // Entire gate cascade depends only on vocab id (h scales uniformly).
        // warp per vocab row; lane = hidden unit j (NH == 32).
        for (int v = warp; v < NVOC; v += NWPC) {
            float scale = 1.f;
#pragma unroll
            for (int l = 0; l < NL; l++) {
                float zb = 0.f;
#pragma unroll
                for (int k = 0; k < NSD; k++)
                    zb = fmaf(emb[v * NEMB + k], w1[(l * NSD + k) * NH + lane], zb);
                float t = fmaxf(fmaf(scale, zb, b1[l * NH + lane]), 0.f) *
                          w2[l * NH + lane];
#pragma unroll
                for (int o = 16; o; o >>= 1) t += __shfl_xor_sync(~0u, t, o);
                float acc = t + b2[l];
                // m=sigmoid(acc); m>0.5 <=> acc>0 -> factor 1 (exact);
                // else factor = 1-m = 1/(1+exp(acc))
                if (!(acc > 0.f)) scale *= 1.f / (1.f + expf(acc));
            }
            if (lane == 0) g_scale[v] = scale;
        }
    } else if (blockIdx.x == 1) {
        // E1[v][j] = emb[v] . pw1[:,j]
        for (int i = tid; i < NVOC * NHID; i += TPB) {
            int v = i / NHID, j = i - v * NHID;
            float a = 0.f;
#pragma unroll 8
            for (int d = 0; d < NEMB; d++)
                a = fmaf(emb[v * NEMB + d], pw1[d * NHID + j], a);
            g_E1[i] = a;
        }
    }

    grid_barrier(&g_bar0);

    // ---------------- Phase B: W[g][v] += scale[v] per node ----------------
    if (tid < NVOC) s_scale[tid] = __ldcg(&g_scale[tid]);
    __syncthreads();

    const int n4 = N >> 2;
    for (int i = gthread; i < n4; i += gsize) {
        int4 a = reinterpret_cast<const int4*>(atoms)[i];
        int4 b = reinterpret_cast<const int4*>(batch)[i];
        atomicAdd(&g_W[b.x * NVOC + a.x], s_scale[a.x]);
        atomicAdd(&g_W[b.y * NVOC + a.y], s_scale[a.y]);
        atomicAdd(&g_W[b.z * NVOC + a.z], s_scale[a.z]);
        atomicAdd(&g_W[b.w * NVOC + a.w], s_scale[a.w]);
    }
    if (gthread == 0)
        for (int n = n4 * 4; n < N; n++)
            atomicAdd(&g_W[batch[n] * NVOC + atoms[n]],
                      __ldcg(&g_scale[atoms[n]]));

    grid_barrier(&g_bar1);

    // ---------------- Phase C: out[g] = relu(W[g]@E1 + pb1)@pw2 + pb2 ------
    for (int i = tid; i < NVOC * NHID; i += TPB) E1s[i] = __ldcg(&g_E1[i]);
    if (tid < NHID) { pb1s[tid] = pb1[tid]; pw2s[tid] = pw2[tid]; }
    const float pb2v = pb2[0];
    __syncthreads();

    const int nwarps = gridDim.x * NWPC;
    const float2* E2 = reinterpret_cast<const float2*>(E1s);
    for (int g = blockIdx.x * NWPC + warp; g < NG; g += nwarps) {
        const float* Wg = g_W + g * NVOC;
        wrow[warp][lane]      = __ldcg(Wg + lane);
        wrow[warp][32 + lane] = __ldcg(Wg + 32 + lane);
        wrow[warp][64 + lane] = __ldcg(Wg + 64 + lane);
        if (lane < 4) wrow[warp][96 + lane] = __ldcg(Wg + 96 + lane);
        __syncwarp();

        float ax = pb1s[2 * lane], ay = pb1s[2 * lane + 1];
#pragma unroll 5
        for (int v = 0; v < NVOC; v++) {
            float wv = wrow[warp][v];          // smem broadcast
            float2 e = E2[v * 32 + lane];      // conflict-free LDS.64
            ax = fmaf(wv, e.x, ax);
            ay = fmaf(wv, e.y, ay);
        }
        float t = fmaf(fmaxf(ax, 0.f), pw2s[2 * lane],
                       fmaxf(ay, 0.f) * pw2s[2 * lane + 1]);
#pragma unroll
        for (int o = 16; o; o >>= 1) t += __shfl_down_sync(~0u, t, o);
        if (lane == 0) out[g] = t + pb2v;
        __syncwarp();                          // before wrow reuse
    }

    // ---------------- Reset barrier counters for the next graph replay -----
    __syncthreads();
    if (tid == 0) {
        __threadfence();
        if (atomicAdd(&g_done, 1u) == gridDim.x - 1) {
            g_bar0 = 0;
            g_bar1 = 0;
            __threadfence();
            g_done = 0;
        }
    }
}

// ---------------------------------------------------------------------------
// Launch: one persistent kernel, exactly 2 CTAs per SM (co-residency
// guaranteed: <=64 regs from launch_bounds, ~33KB static smem per CTA).
// ---------------------------------------------------------------------------
extern "C" void kernel_launch(void* const* d_in, const int* in_sizes, int n_in,
                              void* d_out, int out_size) {
    const int*   atoms = (const int*)d_in[0];
    // d_in[1] pos        : UNUSED by reference
    // d_in[2] edge_index : UNUSED by reference
    const int*   batch = (const int*)d_in[3];
    const float* emb   = (const float*)d_in[4];
    const float* w1    = (const float*)d_in[5];
    const float* b1    = (const float*)d_in[6];
    const float* w2    = (const float*)d_in[7];
    const float* b2    = (const float*)d_in[8];
    const float* pw1   = (const float*)d_in[9];
    const float* pb1   = (const float*)d_in[10];
    const float* pw2   = (const float*)d_in[11];
    const float* pb2   = (const float*)d_in[12];
    int N = in_sizes[0];

    int sm = 148;
    cudaDeviceGetAttribute(&sm, cudaDevAttrMultiProcessorCount, 0);
    int grid = sm * 2;

    fused_kernel<<<grid, TPB>>>(atoms, batch, emb, w1, b1, w2, b2,
                                pw1, pb1, pw2, pb2, (float*)d_out, N);
}

// round 12
// speedup vs baseline: 2.3688x; 2.3688x over previous
#include <cuda_runtime.h>

// Problem constants (fixed-shape problem)
#define NVOC 100     // vocab
#define NL   5       // gate layers
#define NH   32      // gate hidden (== warp size)
#define NSD  16      // s-dim
#define NG   8192    // segments
#define NEMB 128     // embedding dim
#define NHID 64      // EMB/2

// Scratch (__device__ globals; no allocations allowed).
// Both are fully rewritten every replay -> deterministic.
__device__ float g_F[NVOC * NHID];      // F[v] = scale[v] * (emb[v] @ pw1)
__device__ int   g_segstart[NG + 1];    // lower_bound of g in sorted batch

// ---------------------------------------------------------------------------
// Kernel 1 (fused, independent block ranges):
//   blocks [0, nbb)        : segment boundaries from sorted batch
//   blocks [nbb, nbb+NVOC) : F[v][j] = scale[v] * (emb[v] . pw1[:,j])
// ---------------------------------------------------------------------------
__global__ void __launch_bounds__(256)
prep_kernel(const int* __restrict__ batch,
            const float* __restrict__ emb, const float* __restrict__ w1,
            const float* __restrict__ b1,  const float* __restrict__ w2,
            const float* __restrict__ b2,  const float* __restrict__ pw1,
            int N, int nbb) {
    int bid = blockIdx.x;
    if (bid < nbb) {
        // ---- boundaries: seg_start[g] = first i with batch[i] >= g --------
        int i0 = (bid * 256 + threadIdx.x) * 4;   // this thread's 4 nodes
        if (i0 >= N) return;
        int b[5];
        if (i0 + 4 <= N) {
            int4 q = *reinterpret_cast<const int4*>(batch + i0);
            b[0] = q.x; b[1] = q.y; b[2] = q.z; b[3] = q.w;
        } else {
#pragma unroll
            for (int k = 0; k < 4; k++)
                b[k] = (i0 + k < N) ? batch[i0 + k] : 0;
        }
        b[4] = (i0 + 4 < N) ? batch[i0 + 4] : NG;   // sentinel past the end

        if (i0 == 0)
            for (int g = 0; g <= b[0]; g++) g_segstart[g] = 0;
#pragma unroll
        for (int k = 0; k < 4; k++) {
            if (i0 + k >= N) break;
            for (int g = b[k] + 1; g <= b[k + 1]; g++)
                g_segstart[g] = i0 + k + 1;
        }
    } else {
        // ---- F row for vocab v --------------------------------------------
        int v = bid - nbb;
        __shared__ float e1s[NHID];
        __shared__ float s_scale;
        int tid = threadIdx.x;

        if (tid < NHID) {                       // E1[v][j] = emb[v] . pw1[:,j]
            float a = 0.f;
#pragma unroll 8
            for (int d = 0; d < NEMB; d++)
                a = fmaf(emb[v * NEMB + d], pw1[d * NHID + tid], a);
            e1s[tid] = a;
        }
        if (tid < 32) {                         // gate cascade (vocab-only)
            float e[NSD];
#pragma unroll
            for (int k = 0; k < NSD; k++) e[k] = emb[v * NEMB + k];
            float scale = 1.f;
#pragma unroll
            for (int l = 0; l < NL; l++) {
                float zb = 0.f;
#pragma unroll
                for (int k = 0; k < NSD; k++)
                    zb = fmaf(e[k], w1[(l * NSD + k) * NH + tid], zb);
                float t = fmaxf(fmaf(scale, zb, b1[l * NH + tid]), 0.f) *
                          w2[l * NH + tid];
#pragma unroll
                for (int o = 16; o; o >>= 1) t += __shfl_xor_sync(~0u, t, o);
                float acc = t + b2[l];
                // m=sigmoid(acc); m>0.5 <=> acc>0 -> factor 1 (exact);
                // else factor = 1-m = 1/(1+exp(acc))
                if (!(acc > 0.f)) scale *= 1.f / (1.f + expf(acc));
            }
            if (tid == 0) s_scale = scale;
        }
        __syncthreads();
        if (tid < NHID) g_F[v * NHID + tid] = s_scale * e1s[tid];
    }
}

// ---------------------------------------------------------------------------
// Kernel 2: warp per segment.
//   acc[64] = sum over the segment's nodes of F[atom]; then
//   out[g]  = relu(acc + pb1) @ pw2 + pb2
// Hot loop per node: SHFL broadcast + LDS.64 + add.rn.f32x2. No atomics.
// ---------------------------------------------------------------------------
typedef unsigned long long u64;
__device__ __forceinline__ void addx2(u64& acc, u64 f) {
    asm("add.rn.f32x2 %0, %0, %1;" : "+l"(acc) : "l"(f));
}

__global__ void __launch_bounds__(512)
main_kernel(const int* __restrict__ atoms,
            const float* __restrict__ pb1, const float* __restrict__ pw2,
            const float* __restrict__ pb2, float* __restrict__ out) {
    __shared__ float2 F2[NVOC * 32];      // F2[v*32+lane] = dims (2l, 2l+1)
    __shared__ float pb1s[NHID], pw2s[NHID];

    int tid = threadIdx.x;
    for (int i = tid; i < NVOC * 32; i += 512)
        F2[i] = reinterpret_cast<const float2*>(g_F)[i];
    if (tid < NHID) { pb1s[tid] = pb1[tid]; pw2s[tid] = pw2[tid]; }
    float pb2v = pb2[0];
    __syncthreads();

    int warp = tid >> 5, lane = tid & 31;
    int g = blockIdx.x * 16 + warp;
    int s = g_segstart[g], e = g_segstart[g + 1];

    const u64* F8 = reinterpret_cast<const u64*>(F2);
    u64 acc0 = 0ull, acc1 = 0ull;         // packed {0.f, 0.f}

    int nfull = (e - s) & ~31;
    int base  = s;
    for (; base < s + nfull; base += 32) {          // full 32-node blocks
        int a = atoms[base + lane];
#pragma unroll
        for (int k = 0; k < 32; k += 2) {
            int v0 = __shfl_sync(~0u, a, k);
            int v1 = __shfl_sync(~0u, a, k + 1);
            addx2(acc0, F8[v0 * 32 + lane]);
            addx2(acc1, F8[v1 * 32 + lane]);
        }
    }
    int rem = e - base;                              // tail (< 32 nodes)
    if (rem) {
        int a = (lane < rem) ? atoms[base + lane] : 0;
        for (int k = 0; k < rem; k++) {
            int v = __shfl_sync(~0u, a, k);
            if (k & 1) addx2(acc1, F8[v * 32 + lane]);
            else       addx2(acc0, F8[v * 32 + lane]);
        }
    }
    addx2(acc0, acc1);
    float ax = __uint_as_float((unsigned)(acc0 & 0xffffffffull));
    float ay = __uint_as_float((unsigned)(acc0 >> 32));

    float t = fmaf(fmaxf(ax + pb1s[2 * lane], 0.f), pw2s[2 * lane],
                   fmaxf(ay + pb1s[2 * lane + 1], 0.f) * pw2s[2 * lane + 1]);
#pragma unroll
    for (int o = 16; o; o >>= 1) t += __shfl_down_sync(~0u, t, o);
    if (lane == 0) out[g] = t + pb2v;
}

// ---------------------------------------------------------------------------
// Launch: 2 stream-ordered kernels.
// ---------------------------------------------------------------------------
extern "C" void kernel_launch(void* const* d_in, const int* in_sizes, int n_in,
                              void* d_out, int out_size) {
    const int*   atoms = (const int*)d_in[0];
    // d_in[1] pos        : UNUSED by reference
    // d_in[2] edge_index : UNUSED by reference
    const int*   batch = (const int*)d_in[3];
    const float* emb   = (const float*)d_in[4];
    const float* w1    = (const float*)d_in[5];
    const float* b1    = (const float*)d_in[6];
    const float* w2    = (const float*)d_in[7];
    const float* b2    = (const float*)d_in[8];
    const float* pw1   = (const float*)d_in[9];
    // d_in[10] pb1, d_in[11] pw2, d_in[12] pb2 used by main_kernel
    const float* pb1   = (const float*)d_in[10];
    const float* pw2   = (const float*)d_in[11];
    const float* pb2   = (const float*)d_in[12];
    int N = in_sizes[0];

    int nbb = (N + 1023) / 1024;          // 256 threads x 4 nodes per block
    prep_kernel<<<nbb + NVOC, 256>>>(batch, emb, w1, b1, w2, b2, pw1, N, nbb);
    main_kernel<<<NG / 16, 512>>>(atoms, pb1, pw2, pb2, (float*)d_out);
}